// round 8
// baseline (speedup 1.0000x reference)
#include <cuda_runtime.h>
#include <math.h>
#include <stdint.h>

#define NROW 8192
#define DDIM 512
#define BHALF 4096

#define TILE 128
#define NT2 (NROW / TILE)            /* 64 */
#define NPAIR2 (NT2 * (NT2 + 1) / 2) /* 2080 */
#define BKC 64                       /* s8 elems per K-chunk (64 B) */
#define NCH (DDIM / BKC)             /* 8 */

#define QSCALE 24.0f
#define QS2 (QSCALE * QSCALE)

#define SQA_OFF 0
#define SQB_OFF 512
#define RED_OFF 1024
#define TILES_OFF 1280
#define ROW_PITCH 80                 /* 64 B data + 16 B pad (conflict-free) */
#define MAT_BYTES (TILE * ROW_PITCH) /* 10240 */
#define A_OFF 0
#define B_OFF (MAT_BYTES)
#define STAGE_BYTES (2 * MAT_BYTES)  /* 20480 */
#define NSTAGE 3
#define SMEM_TOTAL (TILES_OFF + NSTAGE * STAGE_BYTES) /* 62720 */

__device__ float   g_sq[NROW];
__device__ float   g_colsum[DDIM];
__device__ float   g_totsq;
__device__ double  g_acc[3];
__device__ float   g_negK;           /* -log2(e)/(16*bw) */
__device__ float   g_c2;             /* -2*negK/QS2 */
__device__ int8_t  g_q[NROW * DDIM];

__device__ __forceinline__ uint32_t smem_u32(const void* p) {
    uint32_t a;
    asm("{ .reg .u64 t; cvta.to.shared.u64 t, %1; cvt.u32.u64 %0, t; }"
        : "=r"(a) : "l"(p));
    return a;
}

#define CP_ASYNC16(dst, src) \
    asm volatile("cp.async.cg.shared.global [%0], [%1], 16;" \
                 :: "r"(dst), "l"(src) : "memory")
#define CP_COMMIT() asm volatile("cp.async.commit_group;" ::: "memory")
#define CP_WAIT(n)  asm volatile("cp.async.wait_group %0;" :: "n"(n) : "memory")

#define LDSM_X4(r, a) \
    asm volatile("ldmatrix.sync.aligned.m8n8.x4.shared.b16 {%0,%1,%2,%3}, [%4];" \
                 : "=r"((r)[0]), "=r"((r)[1]), "=r"((r)[2]), "=r"((r)[3]) : "r"(a))

#define IMMA16832(acc, a, b0v, b1v) \
    asm volatile("mma.sync.aligned.m16n8k32.row.col.s32.s8.s8.s32 " \
                 "{%0,%1,%2,%3},{%4,%5,%6,%7},{%8,%9},{%0,%1,%2,%3};" \
                 : "+r"((acc)[0]), "+r"((acc)[1]), "+r"((acc)[2]), "+r"((acc)[3]) \
                 : "r"((a)[0]), "r"((a)[1]), "r"((a)[2]), "r"((a)[3]), \
                   "r"(b0v), "r"(b1v))

/* ---------------------------------------------------------------- init */
__global__ void k_init() {
    int t = threadIdx.x;
    if (t < DDIM) g_colsum[t] = 0.f;
    if (t == 0) {
        g_totsq = 0.f;
        g_acc[0] = 0.0; g_acc[1] = 0.0; g_acc[2] = 0.0;
    }
}

/* -------------------- fused quantize(s8) + rownorm + totsq + colsum -------------------- */
__global__ void k_prep(const float* __restrict__ src, const float* __restrict__ tgt) {
    __shared__ float colacc[8][DDIM];
    __shared__ float bs[8];
    int warp = threadIdx.x >> 5, lane = threadIdx.x & 31;
    int row = blockIdx.x * 8 + warp;
    const float* base = (row < BHALF) ? src + (size_t)row * DDIM
                                      : tgt + (size_t)(row - BHALF) * DDIM;
    size_t orow = (size_t)row * (DDIM / 4);   /* in u32 (4 s8) units */
    float s = 0.f;
#pragma unroll
    for (int ch = 0; ch < 4; ch++) {
        float4 v = *(const float4*)(base + ch * 128 + lane * 4);
        s += v.x * v.x + v.y * v.y + v.z * v.z + v.w * v.w;
        int q0 = __float2int_rn(v.x * QSCALE);
        int q1 = __float2int_rn(v.y * QSCALE);
        int q2 = __float2int_rn(v.z * QSCALE);
        int q3 = __float2int_rn(v.w * QSCALE);
        q0 = max(-127, min(127, q0)); q1 = max(-127, min(127, q1));
        q2 = max(-127, min(127, q2)); q3 = max(-127, min(127, q3));
        uint32_t packed = (uint32_t)(q0 & 0xFF) | ((uint32_t)(q1 & 0xFF) << 8) |
                          ((uint32_t)(q2 & 0xFF) << 16) | ((uint32_t)(q3 & 0xFF) << 24);
        ((uint32_t*)g_q)[orow + ch * 32 + lane] = packed;
        *(float4*)&colacc[warp][ch * 128 + lane * 4] = v;
    }
#pragma unroll
    for (int o = 16; o > 0; o >>= 1) s += __shfl_xor_sync(0xffffffffu, s, o);
    if (lane == 0) { g_sq[row] = s; bs[warp] = s; }
    __syncthreads();

    int c0 = threadIdx.x, c1 = threadIdx.x + 256;
    float s0 = 0.f, s1 = 0.f;
#pragma unroll
    for (int w = 0; w < 8; w++) { s0 += colacc[w][c0]; s1 += colacc[w][c1]; }
    atomicAdd(&g_colsum[c0], s0);
    atomicAdd(&g_colsum[c1], s1);

    if (threadIdx.x == 0) {
        float t = 0.f;
#pragma unroll
        for (int i = 0; i < 8; i++) t += bs[i];
        atomicAdd(&g_totsq, t);
    }
}

/* ---------------------------------------------------------------- bandwidth */
__global__ void k_bw() {
    __shared__ double wred[16];
    int t = threadIdx.x, lane = t & 31, warp = t >> 5;
    double v = (double)g_colsum[t];
    double p = v * v;
#pragma unroll
    for (int o = 16; o > 0; o >>= 1)
        p += __shfl_xor_sync(0xffffffffu, p, o);
    if (lane == 0) wred[warp] = p;
    __syncthreads();
    if (t == 0) {
        double tot = 0.0;
#pragma unroll
        for (int i = 0; i < 16; i++) tot += wred[i];
        double n = (double)NROW;
        double S = 2.0 * n * (double)g_totsq - 2.0 * tot;
        double bw = S / (n * n - n) / 4.0;
        float negK = (float)(-1.4426950408889634 / (16.0 * bw));
        g_negK = negK;
        g_c2 = -2.0f * negK / QS2;
    }
}

/* ---------------------------------------------------------------- chunk loader (128 thr) */
__device__ __forceinline__ void issue_chunk(uint32_t stage_base, int rowA, int rowB,
                                            int kt, int tid) {
    const char* srcA = (const char*)(g_q + (size_t)rowA * DDIM);
    const char* srcB = (const char*)(g_q + (size_t)rowB * DDIM);
    int kbyte = kt * BKC;                 /* 64 B per row per chunk */
#pragma unroll
    for (int i = 0; i < 4; i++) {
        int u = tid + i * 128;            /* 0..511 */
        int r = u >> 2, seg = u & 3;
        size_t go = (size_t)r * DDIM + kbyte + seg * 16;
        uint32_t so = r * ROW_PITCH + seg * 16;
        CP_ASYNC16(stage_base + A_OFF + so, srcA + go);
        CP_ASYNC16(stage_base + B_OFF + so, srcB + go);
    }
    CP_COMMIT();
}

/* ---------------------------------------------------------------- main IMMA kernel */
__global__ void __launch_bounds__(128, 2) k_gemm() {
    extern __shared__ char smem[];
    int tid = threadIdx.x;
    int lane = tid & 31, wid = tid >> 5;
    int wr = wid >> 1, wc = wid & 1;     /* 2x2 grid of 64x64 warp tiles */

    int t = blockIdx.x;
    int bi = 0, rem = t;
    while (rem >= NT2 - bi) { rem -= NT2 - bi; bi++; }
    int bj = bi + rem;
    int rowA = bi * TILE, rowB = bj * TILE;

    uint32_t sbase = smem_u32(smem);
    float* sqA = (float*)(smem + SQA_OFF);
    float* sqB = (float*)(smem + SQB_OFF);
    float* red = (float*)(smem + RED_OFF);

    if (tid < TILE) {
        sqA[tid] = g_sq[rowA + tid];
        sqB[tid] = g_sq[rowB + tid];
    }

    /* ldmatrix lane addressing (byte-identical to proven fp16 mapping) */
    uint32_t aRow = wr * 64 + (lane & 7) + (lane & 8);
    uint32_t aColB = (lane & 16);                       /* byte offset 0/16 */
    uint32_t bN = wc * 64 + (lane & 7) + ((lane & 16) >> 1);
    uint32_t bColB = (lane & 8) * 2;                    /* byte offset 0/16 */

    int acc[4][8][4];
#pragma unroll
    for (int r = 0; r < 4; r++)
#pragma unroll
        for (int j = 0; j < 8; j++)
#pragma unroll
            for (int e = 0; e < 4; e++) acc[r][j][e] = 0;

    uint32_t tb = sbase + TILES_OFF;
    issue_chunk(tb, rowA, rowB, 0, tid);
    issue_chunk(tb + STAGE_BYTES, rowA, rowB, 1, tid);

    uint32_t ah[2][4][4], bh[2][4][4];

    int sidx = 0;
    for (int kt = 0; kt < NCH; kt++) {
        if (kt < NCH - 1) CP_WAIT(1); else CP_WAIT(0);
        __syncthreads();
        if (kt + 2 < NCH) {
            int ns = sidx + 2; if (ns >= NSTAGE) ns -= NSTAGE;
            issue_chunk(tb + ns * STAGE_BYTES, rowA, rowB, kt + 2, tid);
        }

        uint32_t S = tb + sidx * STAGE_BYTES;

        /* ks0: K bytes [0,32) ; ks1: [32,64) */
#pragma unroll
        for (int rt = 0; rt < 4; rt++)
            LDSM_X4(ah[0][rt], S + A_OFF + (aRow + rt * 16) * ROW_PITCH + aColB);
#pragma unroll
        for (int jp = 0; jp < 4; jp++)
            LDSM_X4(bh[0][jp], S + B_OFF + (bN + jp * 16) * ROW_PITCH + bColB);
#pragma unroll
        for (int rt = 0; rt < 4; rt++)
            LDSM_X4(ah[1][rt], S + A_OFF + (aRow + rt * 16) * ROW_PITCH + 32 + aColB);
#pragma unroll
        for (int jp = 0; jp < 4; jp++)
            LDSM_X4(bh[1][jp], S + B_OFF + (bN + jp * 16) * ROW_PITCH + 32 + bColB);

#pragma unroll
        for (int rt = 0; rt < 4; rt++)
#pragma unroll
            for (int jp = 0; jp < 4; jp++) {
                IMMA16832(acc[rt][jp * 2],     ah[0][rt], bh[0][jp][0], bh[0][jp][1]);
                IMMA16832(acc[rt][jp * 2 + 1], ah[0][rt], bh[0][jp][2], bh[0][jp][3]);
            }
#pragma unroll
        for (int rt = 0; rt < 4; rt++)
#pragma unroll
            for (int jp = 0; jp < 4; jp++) {
                IMMA16832(acc[rt][jp * 2],     ah[1][rt], bh[1][jp][0], bh[1][jp][1]);
                IMMA16832(acc[rt][jp * 2 + 1], ah[1][rt], bh[1][jp][2], bh[1][jp][3]);
            }

        sidx++; if (sidx >= NSTAGE) sidx = 0;
    }

    /* -------- fused epilogue: arg = (sqi+sqj)*negK + dot_int*c2 -------- */
    float negK = g_negK;
    float c2 = g_c2;
    int g = lane >> 2, tg = lane & 3;
    float rowsq[4][2], colsq[8][2];
#pragma unroll
    for (int rt = 0; rt < 4; rt++) {
        rowsq[rt][0] = sqA[wr * 64 + rt * 16 + g] * negK;
        rowsq[rt][1] = sqA[wr * 64 + rt * 16 + g + 8] * negK;
    }
#pragma unroll
    for (int j = 0; j < 8; j++) {
        colsq[j][0] = sqB[wc * 64 + j * 8 + 2 * tg] * negK;
        colsq[j][1] = sqB[wc * 64 + j * 8 + 2 * tg + 1] * negK;
    }

    float tsum = 0.f;
#pragma unroll
    for (int rt = 0; rt < 4; rt++) {
#pragma unroll
        for (int j = 0; j < 8; j++) {
#pragma unroll
            for (int e = 0; e < 4; e++) {
                float arg = fmaf(c2, (float)acc[rt][j][e],
                                 rowsq[rt][e >> 1] + colsq[j][e & 1]);
                float s;
                asm("ex2.approx.f32 %0, %1;" : "=f"(s) : "f"(arg));
                float s2 = s * s, s4 = s2 * s2, s8 = s4 * s4, s16 = s8 * s8;
                tsum += ((s + s2) + (s4 + s8)) + s16;
            }
        }
    }
#pragma unroll
    for (int o = 16; o > 0; o >>= 1) tsum += __shfl_xor_sync(0xffffffffu, tsum, o);
    if (lane == 0) red[wid] = tsum;
    __syncthreads();
    if (tid == 0) {
        float tot = red[0] + red[1] + red[2] + red[3];
        double w = (bi == bj) ? 1.0 : 2.0;
        int qidx = (bi < NT2 / 2) ? ((bj < NT2 / 2) ? 0 : 2) : 1;
        atomicAdd(&g_acc[qidx], w * (double)tot);
    }
}

/* ---------------------------------------------------------------- final */
__global__ void k_final(float* out) {
    double bb = (double)BHALF * (double)BHALF;
    out[0] = (float)((g_acc[0] + g_acc[1] - g_acc[2]) / bb);
}

/* ---------------------------------------------------------------- launch */
extern "C" void kernel_launch(void* const* d_in, const int* in_sizes, int n_in,
                              void* d_out, int out_size) {
    const float* src = (const float*)d_in[0];
    const float* tgt = (const float*)d_in[1];
    float* out = (float*)d_out;

    cudaFuncSetAttribute(k_gemm, cudaFuncAttributeMaxDynamicSharedMemorySize, SMEM_TOTAL);

    k_init<<<1, 512>>>();
    k_prep<<<NROW / 8, 256>>>(src, tgt);
    k_bw<<<1, 512>>>();
    k_gemm<<<NPAIR2, 128, SMEM_TOTAL>>>();
    k_final<<<1, 1>>>(out);
}

// round 9
// speedup vs baseline: 2.0907x; 2.0907x over previous
#include <cuda_runtime.h>
#include <cuda_fp16.h>
#include <math.h>
#include <stdint.h>

#define NROW 8192
#define DDIM 512
#define BHALF 4096

#define TILE 128
#define NT2 (NROW / TILE)            /* 64 */
#define NPAIR2 (NT2 * (NT2 + 1) / 2) /* 2080 */
#define BKC 32                       /* fp16 per K-chunk */
#define NCH (DDIM / BKC)             /* 16 */

#define SQA_OFF 0
#define SQB_OFF 512
#define RED_OFF 1024
#define TILES_OFF 1280
#define ROW_PITCH 80                 /* 32 fp16 = 64B + 16B pad (conflict-free) */
#define MAT_BYTES (TILE * ROW_PITCH) /* 10240 */
#define A_OFF 0
#define B_OFF (MAT_BYTES)
#define STAGE_BYTES (2 * MAT_BYTES)  /* 20480 */
#define NSTAGE 3
#define SMEM_TOTAL (TILES_OFF + NSTAGE * STAGE_BYTES) /* 62720 */

__device__ float  g_sq[NROW];
__device__ float  g_colsum[DDIM];    /* zeroed by k_bw after use (self-cleaning) */
__device__ float  g_totsq;
__device__ double g_acc[3];          /* reset by the finishing k_gemm block */
__device__ float  g_negK;            /* -log2(e)/(16*bw) */
__device__ int    g_cnt;             /* finisher counter; reset by finisher */
__device__ __half g_h[NROW * DDIM];

__device__ __forceinline__ uint32_t smem_u32(const void* p) {
    uint32_t a;
    asm("{ .reg .u64 t; cvta.to.shared.u64 t, %1; cvt.u32.u64 %0, t; }"
        : "=r"(a) : "l"(p));
    return a;
}

#define CP_ASYNC16(dst, src) \
    asm volatile("cp.async.cg.shared.global [%0], [%1], 16;" \
                 :: "r"(dst), "l"(src) : "memory")
#define CP_COMMIT() asm volatile("cp.async.commit_group;" ::: "memory")
#define CP_WAIT(n)  asm volatile("cp.async.wait_group %0;" :: "n"(n) : "memory")

#define LDSM_X4(r, a) \
    asm volatile("ldmatrix.sync.aligned.m8n8.x4.shared.b16 {%0,%1,%2,%3}, [%4];" \
                 : "=r"((r)[0]), "=r"((r)[1]), "=r"((r)[2]), "=r"((r)[3]) : "r"(a))

#define MMA16816(acc, a, b0v, b1v) \
    asm volatile("mma.sync.aligned.m16n8k16.row.col.f32.f16.f16.f32 " \
                 "{%0,%1,%2,%3},{%4,%5,%6,%7},{%8,%9},{%0,%1,%2,%3};" \
                 : "+f"((acc)[0]), "+f"((acc)[1]), "+f"((acc)[2]), "+f"((acc)[3]) \
                 : "r"((a)[0]), "r"((a)[1]), "r"((a)[2]), "r"((a)[3]), \
                   "r"(b0v), "r"(b1v))

/* -------------------- fused split(fp16) + rownorm + totsq + colsum -------------------- */
__global__ void k_prep(const float* __restrict__ src, const float* __restrict__ tgt) {
    __shared__ float colacc[8][DDIM];
    __shared__ float bs[8];
    int warp = threadIdx.x >> 5, lane = threadIdx.x & 31;
    int row = blockIdx.x * 8 + warp;
    const float* base = (row < BHALF) ? src + (size_t)row * DDIM
                                      : tgt + (size_t)(row - BHALF) * DDIM;
    size_t orow = (size_t)row * (DDIM / 4);
    float s = 0.f;
#pragma unroll
    for (int ch = 0; ch < 4; ch++) {
        float4 v = *(const float4*)(base + ch * 128 + lane * 4);
        s += v.x * v.x + v.y * v.y + v.z * v.z + v.w * v.w;
        __half2 p0 = __floats2half2_rn(v.x, v.y);
        __half2 p1 = __floats2half2_rn(v.z, v.w);
        uint2 hv;
        hv.x = *(uint32_t*)&p0; hv.y = *(uint32_t*)&p1;
        ((uint2*)g_h)[orow + ch * 32 + lane] = hv;
        *(float4*)&colacc[warp][ch * 128 + lane * 4] = v;
    }
#pragma unroll
    for (int o = 16; o > 0; o >>= 1) s += __shfl_xor_sync(0xffffffffu, s, o);
    if (lane == 0) { g_sq[row] = s; bs[warp] = s; }
    __syncthreads();

    int c0 = threadIdx.x, c1 = threadIdx.x + 256;
    float s0 = 0.f, s1 = 0.f;
#pragma unroll
    for (int w = 0; w < 8; w++) { s0 += colacc[w][c0]; s1 += colacc[w][c1]; }
    atomicAdd(&g_colsum[c0], s0);
    atomicAdd(&g_colsum[c1], s1);

    if (threadIdx.x == 0) {
        float t = 0.f;
#pragma unroll
        for (int i = 0; i < 8; i++) t += bs[i];
        atomicAdd(&g_totsq, t);
    }
}

/* ------------------- bandwidth (also self-cleans colsum/totsq) ------------------- */
__global__ void k_bw() {
    __shared__ double wred[16];
    int t = threadIdx.x, lane = t & 31, warp = t >> 5;
    float cs = g_colsum[t];
    double v = (double)cs;
    double p = v * v;
#pragma unroll
    for (int o = 16; o > 0; o >>= 1)
        p += __shfl_xor_sync(0xffffffffu, p, o);
    if (lane == 0) wred[warp] = p;
    __syncthreads();
    if (t == 0) {
        double tot = 0.0;
#pragma unroll
        for (int i = 0; i < 16; i++) tot += wred[i];
        double n = (double)NROW;
        double S = 2.0 * n * (double)g_totsq - 2.0 * tot;
        double bw = S / (n * n - n) / 4.0;
        g_negK = (float)(-1.4426950408889634 / (16.0 * bw));
        g_totsq = 0.f;                 /* clean for next replay */
    }
    g_colsum[t] = 0.f;                 /* clean for next replay */
}

/* ---------------------------------------------------------------- chunk loader (128 thr) */
__device__ __forceinline__ void issue_chunk(uint32_t stage_base, int rowA, int rowB,
                                            int kt, int tid) {
    const char* srcA = (const char*)(g_h + (size_t)rowA * DDIM);
    const char* srcB = (const char*)(g_h + (size_t)rowB * DDIM);
    int kbyte = kt * (BKC * 2);
#pragma unroll
    for (int i = 0; i < 4; i++) {
        int u = tid + i * 128;
        int r = u >> 2, seg = u & 3;
        size_t go = (size_t)r * (DDIM * 2) + kbyte + seg * 16;
        uint32_t so = r * ROW_PITCH + seg * 16;
        CP_ASYNC16(stage_base + A_OFF + so, srcA + go);
        CP_ASYNC16(stage_base + B_OFF + so, srcB + go);
    }
    CP_COMMIT();
}

/* ---------------------------------------------------------------- main HMMA kernel */
__global__ void __launch_bounds__(128, 2) k_gemm(float* out) {
    extern __shared__ char smem[];
    int tid = threadIdx.x;
    int lane = tid & 31, wid = tid >> 5;
    int wr = wid >> 1, wc = wid & 1;     /* 2x2 grid of 64x64 warp tiles */

    int t = blockIdx.x;
    int bi = 0, rem = t;
    while (rem >= NT2 - bi) { rem -= NT2 - bi; bi++; }
    int bj = bi + rem;
    int rowA = bi * TILE, rowB = bj * TILE;

    uint32_t sbase = smem_u32(smem);
    float* sqA = (float*)(smem + SQA_OFF);
    float* sqB = (float*)(smem + SQB_OFF);
    float* red = (float*)(smem + RED_OFF);

    if (tid < TILE) {
        sqA[tid] = g_sq[rowA + tid];
        sqB[tid] = g_sq[rowB + tid];
    }

    uint32_t aRow = wr * 64 + (lane & 7) + (lane & 8);
    uint32_t aColH = (lane & 16) >> 1;
    uint32_t bN = wc * 64 + (lane & 7) + ((lane & 16) >> 1);
    uint32_t bKoff = (lane & 8);

    float acc[4][8][4];
#pragma unroll
    for (int r = 0; r < 4; r++)
#pragma unroll
        for (int j = 0; j < 8; j++)
#pragma unroll
            for (int e = 0; e < 4; e++) acc[r][j][e] = 0.f;

    uint32_t tb = sbase + TILES_OFF;
    issue_chunk(tb, rowA, rowB, 0, tid);
    issue_chunk(tb + STAGE_BYTES, rowA, rowB, 1, tid);

    uint32_t ah[2][4][4], bh[2][4][4];

    int sidx = 0;
    for (int kt = 0; kt < NCH; kt++) {
        if (kt < NCH - 1) CP_WAIT(1); else CP_WAIT(0);
        __syncthreads();
        if (kt + 2 < NCH) {
            int ns = sidx + 2; if (ns >= NSTAGE) ns -= NSTAGE;
            issue_chunk(tb + ns * STAGE_BYTES, rowA, rowB, kt + 2, tid);
        }

        uint32_t S = tb + sidx * STAGE_BYTES;

#pragma unroll
        for (int rt = 0; rt < 4; rt++)
            LDSM_X4(ah[0][rt], S + A_OFF + (aRow + rt * 16) * ROW_PITCH + aColH * 2);
#pragma unroll
        for (int jp = 0; jp < 4; jp++)
            LDSM_X4(bh[0][jp], S + B_OFF + (bN + jp * 16) * ROW_PITCH + bKoff * 2);
#pragma unroll
        for (int rt = 0; rt < 4; rt++)
            LDSM_X4(ah[1][rt], S + A_OFF + (aRow + rt * 16) * ROW_PITCH + (16 + aColH) * 2);
#pragma unroll
        for (int jp = 0; jp < 4; jp++)
            LDSM_X4(bh[1][jp], S + B_OFF + (bN + jp * 16) * ROW_PITCH + (16 + bKoff) * 2);

#pragma unroll
        for (int rt = 0; rt < 4; rt++)
#pragma unroll
            for (int jp = 0; jp < 4; jp++) {
                MMA16816(acc[rt][jp * 2],     ah[0][rt], bh[0][jp][0], bh[0][jp][1]);
                MMA16816(acc[rt][jp * 2 + 1], ah[0][rt], bh[0][jp][2], bh[0][jp][3]);
            }
#pragma unroll
        for (int rt = 0; rt < 4; rt++)
#pragma unroll
            for (int jp = 0; jp < 4; jp++) {
                MMA16816(acc[rt][jp * 2],     ah[1][rt], bh[1][jp][0], bh[1][jp][1]);
                MMA16816(acc[rt][jp * 2 + 1], ah[1][rt], bh[1][jp][2], bh[1][jp][3]);
            }

        sidx++; if (sidx >= NSTAGE) sidx = 0;
    }

    /* -------- fused epilogue -------- */
    float negK = g_negK;
    int g = lane >> 2, tg = lane & 3;
    float rowsq[4][2], colsq[8][2];
#pragma unroll
    for (int rt = 0; rt < 4; rt++) {
        rowsq[rt][0] = sqA[wr * 64 + rt * 16 + g];
        rowsq[rt][1] = sqA[wr * 64 + rt * 16 + g + 8];
    }
#pragma unroll
    for (int j = 0; j < 8; j++) {
        colsq[j][0] = sqB[wc * 64 + j * 8 + 2 * tg];
        colsq[j][1] = sqB[wc * 64 + j * 8 + 2 * tg + 1];
    }

    float tsum = 0.f;
#pragma unroll
    for (int rt = 0; rt < 4; rt++) {
#pragma unroll
        for (int j = 0; j < 8; j++) {
#pragma unroll
            for (int e = 0; e < 4; e++) {
                float sq2 = rowsq[rt][e >> 1] + colsq[j][e & 1];
                float L2v = fmaf(-2.f, acc[rt][j][e], sq2);
                float s;
                asm("ex2.approx.f32 %0, %1;" : "=f"(s) : "f"(L2v * negK));
                float s2 = s * s, s4 = s2 * s2, s8 = s4 * s4, s16 = s8 * s8;
                tsum += ((s + s2) + (s4 + s8)) + s16;
            }
        }
    }
#pragma unroll
    for (int o = 16; o > 0; o >>= 1) tsum += __shfl_xor_sync(0xffffffffu, tsum, o);
    if (lane == 0) red[wid] = tsum;
    __syncthreads();

    if (tid == 0) {
        float tot = red[0] + red[1] + red[2] + red[3];
        double w = (bi == bj) ? 1.0 : 2.0;
        int qidx = (bi < NT2 / 2) ? ((bj < NT2 / 2) ? 0 : 2) : 1;
        atomicAdd(&g_acc[qidx], w * (double)tot);

        /* finisher: last block to complete computes the output */
        __threadfence();
        int prev = atomicAdd(&g_cnt, 1);
        if (prev == NPAIR2 - 1) {
            double bb = (double)BHALF * (double)BHALF;
            out[0] = (float)((g_acc[0] + g_acc[1] - g_acc[2]) / bb);
            g_acc[0] = 0.0; g_acc[1] = 0.0; g_acc[2] = 0.0;  /* clean for next replay */
            g_cnt = 0;
        }
    }
}

/* ---------------------------------------------------------------- launch */
extern "C" void kernel_launch(void* const* d_in, const int* in_sizes, int n_in,
                              void* d_out, int out_size) {
    const float* src = (const float*)d_in[0];
    const float* tgt = (const float*)d_in[1];
    float* out = (float*)d_out;

    cudaFuncSetAttribute(k_gemm, cudaFuncAttributeMaxDynamicSharedMemorySize, SMEM_TOTAL);

    k_prep<<<NROW / 8, 256>>>(src, tgt);
    k_bw<<<1, 512>>>();
    k_gemm<<<NPAIR2, 128, SMEM_TOTAL>>>(out);
}

// round 10
// speedup vs baseline: 2.2744x; 1.0879x over previous
#include <cuda_runtime.h>
#include <cuda_fp16.h>
#include <math.h>
#include <stdint.h>

#define NROW 8192
#define DDIM 512
#define BHALF 4096

#define TILE 128
#define NT2 (NROW / TILE)            /* 64 */
#define NPAIR2 (NT2 * (NT2 + 1) / 2) /* 2080 */
#define BKC 32                       /* fp16 per K-chunk */
#define NCH (DDIM / BKC)             /* 16 */

#define SQA_OFF 0
#define SQB_OFF 512
#define RED_OFF 1024
#define TILES_OFF 1280
#define ROW_PITCH 80                 /* 32 fp16 = 64B + 16B pad (conflict-free) */
#define MAT_BYTES (TILE * ROW_PITCH) /* 10240 */
#define A_OFF 0
#define B_OFF (MAT_BYTES)
#define STAGE_BYTES (2 * MAT_BYTES)  /* 20480 */
#define NSTAGE 3
#define SMEM_TOTAL (TILES_OFF + NSTAGE * STAGE_BYTES) /* 62720 */

__device__ float  g_sq[NROW];
__device__ float  g_colsum[DDIM];    /* zeroed by k_bw after use (self-cleaning) */
__device__ float  g_totsq;
__device__ double g_acc[3];          /* reset by the finishing k_gemm block */
__device__ float  g_negK;            /* -log2(e)/(16*bw) */
__device__ int    g_cnt;             /* finisher counter; reset by finisher */
__device__ __half g_h[NROW * DDIM];

__device__ __forceinline__ uint32_t smem_u32(const void* p) {
    uint32_t a;
    asm("{ .reg .u64 t; cvta.to.shared.u64 t, %1; cvt.u32.u64 %0, t; }"
        : "=r"(a) : "l"(p));
    return a;
}

#define CP_ASYNC16(dst, src) \
    asm volatile("cp.async.cg.shared.global [%0], [%1], 16;" \
                 :: "r"(dst), "l"(src) : "memory")
#define CP_COMMIT() asm volatile("cp.async.commit_group;" ::: "memory")
#define CP_WAIT(n)  asm volatile("cp.async.wait_group %0;" :: "n"(n) : "memory")

#define LDSM_X4(r, a) \
    asm volatile("ldmatrix.sync.aligned.m8n8.x4.shared.b16 {%0,%1,%2,%3}, [%4];" \
                 : "=r"((r)[0]), "=r"((r)[1]), "=r"((r)[2]), "=r"((r)[3]) : "r"(a))

/* fp16-accumulator HMMA: C/D are 2 packed-b32 regs (4 halves) */
#define MMA16816H(acc, a, b0v, b1v) \
    asm volatile("mma.sync.aligned.m16n8k16.row.col.f16.f16.f16.f16 " \
                 "{%0,%1},{%2,%3,%4,%5},{%6,%7},{%0,%1};" \
                 : "+r"((acc)[0]), "+r"((acc)[1]) \
                 : "r"((a)[0]), "r"((a)[1]), "r"((a)[2]), "r"((a)[3]), \
                   "r"(b0v), "r"(b1v))

/* -------------------- fused split(fp16) + rownorm + totsq + colsum -------------------- */
__global__ void k_prep(const float* __restrict__ src, const float* __restrict__ tgt) {
    __shared__ float colacc[8][DDIM];
    __shared__ float bs[8];
    int warp = threadIdx.x >> 5, lane = threadIdx.x & 31;
    int row = blockIdx.x * 8 + warp;
    const float* base = (row < BHALF) ? src + (size_t)row * DDIM
                                      : tgt + (size_t)(row - BHALF) * DDIM;
    size_t orow = (size_t)row * (DDIM / 4);
    float s = 0.f;
#pragma unroll
    for (int ch = 0; ch < 4; ch++) {
        float4 v = *(const float4*)(base + ch * 128 + lane * 4);
        s += v.x * v.x + v.y * v.y + v.z * v.z + v.w * v.w;
        __half2 p0 = __floats2half2_rn(v.x, v.y);
        __half2 p1 = __floats2half2_rn(v.z, v.w);
        uint2 hv;
        hv.x = *(uint32_t*)&p0; hv.y = *(uint32_t*)&p1;
        ((uint2*)g_h)[orow + ch * 32 + lane] = hv;
        *(float4*)&colacc[warp][ch * 128 + lane * 4] = v;
    }
#pragma unroll
    for (int o = 16; o > 0; o >>= 1) s += __shfl_xor_sync(0xffffffffu, s, o);
    if (lane == 0) { g_sq[row] = s; bs[warp] = s; }
    __syncthreads();

    int c0 = threadIdx.x, c1 = threadIdx.x + 256;
    float s0 = 0.f, s1 = 0.f;
#pragma unroll
    for (int w = 0; w < 8; w++) { s0 += colacc[w][c0]; s1 += colacc[w][c1]; }
    atomicAdd(&g_colsum[c0], s0);
    atomicAdd(&g_colsum[c1], s1);

    if (threadIdx.x == 0) {
        float t = 0.f;
#pragma unroll
        for (int i = 0; i < 8; i++) t += bs[i];
        atomicAdd(&g_totsq, t);
    }
}

/* ------------------- bandwidth (also self-cleans colsum/totsq) ------------------- */
__global__ void k_bw() {
    __shared__ double wred[16];
    int t = threadIdx.x, lane = t & 31, warp = t >> 5;
    float cs = g_colsum[t];
    double v = (double)cs;
    double p = v * v;
#pragma unroll
    for (int o = 16; o > 0; o >>= 1)
        p += __shfl_xor_sync(0xffffffffu, p, o);
    if (lane == 0) wred[warp] = p;
    __syncthreads();
    if (t == 0) {
        double tot = 0.0;
#pragma unroll
        for (int i = 0; i < 16; i++) tot += wred[i];
        double n = (double)NROW;
        double S = 2.0 * n * (double)g_totsq - 2.0 * tot;
        double bw = S / (n * n - n) / 4.0;
        g_negK = (float)(-1.4426950408889634 / (16.0 * bw));
        g_totsq = 0.f;
    }
    g_colsum[t] = 0.f;
}

/* ---------------------------------------------------------------- chunk loader (128 thr) */
__device__ __forceinline__ void issue_chunk(uint32_t stage_base, int rowA, int rowB,
                                            int kt, int tid) {
    const char* srcA = (const char*)(g_h + (size_t)rowA * DDIM);
    const char* srcB = (const char*)(g_h + (size_t)rowB * DDIM);
    int kbyte = kt * (BKC * 2);
#pragma unroll
    for (int i = 0; i < 4; i++) {
        int u = tid + i * 128;
        int r = u >> 2, seg = u & 3;
        size_t go = (size_t)r * (DDIM * 2) + kbyte + seg * 16;
        uint32_t so = r * ROW_PITCH + seg * 16;
        CP_ASYNC16(stage_base + A_OFF + so, srcA + go);
        CP_ASYNC16(stage_base + B_OFF + so, srcB + go);
    }
    CP_COMMIT();
}

/* ---------------------------------------------------------------- main HMMA kernel */
__global__ void __launch_bounds__(128, 2) k_gemm(float* out) {
    extern __shared__ char smem[];
    int tid = threadIdx.x;
    int lane = tid & 31, wid = tid >> 5;
    int wr = wid >> 1, wc = wid & 1;     /* 2x2 grid of 64x64 warp tiles */

    int t = blockIdx.x;
    int bi = 0, rem = t;
    while (rem >= NT2 - bi) { rem -= NT2 - bi; bi++; }
    int bj = bi + rem;
    int rowA = bi * TILE, rowB = bj * TILE;

    uint32_t sbase = smem_u32(smem);
    float* sqA = (float*)(smem + SQA_OFF);
    float* sqB = (float*)(smem + SQB_OFF);
    float* red = (float*)(smem + RED_OFF);

    if (tid < TILE) {
        sqA[tid] = g_sq[rowA + tid];
        sqB[tid] = g_sq[rowB + tid];
    }

    uint32_t aRow = wr * 64 + (lane & 7) + (lane & 8);
    uint32_t aColH = (lane & 16) >> 1;
    uint32_t bN = wc * 64 + (lane & 7) + ((lane & 16) >> 1);
    uint32_t bKoff = (lane & 8);

    /* packed fp16 accumulators: [rt][j][2] regs, 4 halves each */
    uint32_t acc[4][8][2];
#pragma unroll
    for (int r = 0; r < 4; r++)
#pragma unroll
        for (int j = 0; j < 8; j++) { acc[r][j][0] = 0u; acc[r][j][1] = 0u; }

    uint32_t tb = sbase + TILES_OFF;
    issue_chunk(tb, rowA, rowB, 0, tid);
    issue_chunk(tb + STAGE_BYTES, rowA, rowB, 1, tid);

    uint32_t ah[2][4][4], bh[2][4][4];

    int sidx = 0;
    for (int kt = 0; kt < NCH; kt++) {
        if (kt < NCH - 1) CP_WAIT(1); else CP_WAIT(0);
        __syncthreads();
        if (kt + 2 < NCH) {
            int ns = sidx + 2; if (ns >= NSTAGE) ns -= NSTAGE;
            issue_chunk(tb + ns * STAGE_BYTES, rowA, rowB, kt + 2, tid);
        }

        uint32_t S = tb + sidx * STAGE_BYTES;

#pragma unroll
        for (int rt = 0; rt < 4; rt++)
            LDSM_X4(ah[0][rt], S + A_OFF + (aRow + rt * 16) * ROW_PITCH + aColH * 2);
#pragma unroll
        for (int jp = 0; jp < 4; jp++)
            LDSM_X4(bh[0][jp], S + B_OFF + (bN + jp * 16) * ROW_PITCH + bKoff * 2);
#pragma unroll
        for (int rt = 0; rt < 4; rt++)
            LDSM_X4(ah[1][rt], S + A_OFF + (aRow + rt * 16) * ROW_PITCH + (16 + aColH) * 2);
#pragma unroll
        for (int jp = 0; jp < 4; jp++)
            LDSM_X4(bh[1][jp], S + B_OFF + (bN + jp * 16) * ROW_PITCH + (16 + bKoff) * 2);

#pragma unroll
        for (int rt = 0; rt < 4; rt++)
#pragma unroll
            for (int jp = 0; jp < 4; jp++) {
                MMA16816H(acc[rt][jp * 2],     ah[0][rt], bh[0][jp][0], bh[0][jp][1]);
                MMA16816H(acc[rt][jp * 2 + 1], ah[0][rt], bh[0][jp][2], bh[0][jp][3]);
            }
#pragma unroll
        for (int rt = 0; rt < 4; rt++)
#pragma unroll
            for (int jp = 0; jp < 4; jp++) {
                MMA16816H(acc[rt][jp * 2],     ah[1][rt], bh[1][jp][0], bh[1][jp][1]);
                MMA16816H(acc[rt][jp * 2 + 1], ah[1][rt], bh[1][jp][2], bh[1][jp][3]);
            }

        sidx++; if (sidx >= NSTAGE) sidx = 0;
    }

    /* -------- fused epilogue (promote fp16 acc -> fp32 here) -------- */
    float negK = g_negK;
    int g = lane >> 2, tg = lane & 3;
    float rowsq[4][2], colsq[8][2];
#pragma unroll
    for (int rt = 0; rt < 4; rt++) {
        rowsq[rt][0] = sqA[wr * 64 + rt * 16 + g];
        rowsq[rt][1] = sqA[wr * 64 + rt * 16 + g + 8];
    }
#pragma unroll
    for (int j = 0; j < 8; j++) {
        colsq[j][0] = sqB[wc * 64 + j * 8 + 2 * tg];
        colsq[j][1] = sqB[wc * 64 + j * 8 + 2 * tg + 1];
    }

    float tsum = 0.f;
#pragma unroll
    for (int rt = 0; rt < 4; rt++) {
#pragma unroll
        for (int j = 0; j < 8; j++) {
            /* reg0 = (row g, cols 2tg/2tg+1); reg1 = (row g+8, same cols) */
            float2 d01 = __half22float2(*(__half2*)&acc[rt][j][0]);
            float2 d23 = __half22float2(*(__half2*)&acc[rt][j][1]);
            float dv[4] = { d01.x, d01.y, d23.x, d23.y };
#pragma unroll
            for (int e = 0; e < 4; e++) {
                float sq2 = rowsq[rt][e >> 1] + colsq[j][e & 1];
                float L2v = fmaf(-2.f, dv[e], sq2);
                float s;
                asm("ex2.approx.f32 %0, %1;" : "=f"(s) : "f"(L2v * negK));
                float s2 = s * s, s4 = s2 * s2, s8 = s4 * s4, s16 = s8 * s8;
                tsum += ((s + s2) + (s4 + s8)) + s16;
            }
        }
    }
#pragma unroll
    for (int o = 16; o > 0; o >>= 1) tsum += __shfl_xor_sync(0xffffffffu, tsum, o);
    if (lane == 0) red[wid] = tsum;
    __syncthreads();

    if (tid == 0) {
        float tot = red[0] + red[1] + red[2] + red[3];
        double w = (bi == bj) ? 1.0 : 2.0;
        int qidx = (bi < NT2 / 2) ? ((bj < NT2 / 2) ? 0 : 2) : 1;
        atomicAdd(&g_acc[qidx], w * (double)tot);

        __threadfence();
        int prev = atomicAdd(&g_cnt, 1);
        if (prev == NPAIR2 - 1) {
            double bb = (double)BHALF * (double)BHALF;
            out[0] = (float)((g_acc[0] + g_acc[1] - g_acc[2]) / bb);
            g_acc[0] = 0.0; g_acc[1] = 0.0; g_acc[2] = 0.0;
            g_cnt = 0;
        }
    }
}

/* ---------------------------------------------------------------- launch */
extern "C" void kernel_launch(void* const* d_in, const int* in_sizes, int n_in,
                              void* d_out, int out_size) {
    const float* src = (const float*)d_in[0];
    const float* tgt = (const float*)d_in[1];
    float* out = (float*)d_out;

    cudaFuncSetAttribute(k_gemm, cudaFuncAttributeMaxDynamicSharedMemorySize, SMEM_TOTAL);

    k_prep<<<NROW / 8, 256>>>(src, tgt);
    k_bw<<<1, 512>>>();
    k_gemm<<<NPAIR2, 128, SMEM_TOTAL>>>(out);
}

// round 15
// speedup vs baseline: 2.3055x; 1.0137x over previous
#include <cuda_runtime.h>
#include <cuda_fp16.h>
#include <math.h>
#include <stdint.h>

#define NROW 8192
#define DDIM 512
#define BHALF 4096

#define TILE 128
#define NT2 (NROW / TILE)            /* 64 */
#define NPAIR2 (NT2 * (NT2 + 1) / 2) /* 2080 */
#define BKC 32                       /* fp16 per K-chunk */
#define NCH (DDIM / BKC)             /* 16 */

#define SQA_OFF 0
#define SQB_OFF 512
#define RED_OFF 1024
#define TILES_OFF 1280
#define ROW_PITCH 80                 /* 32 fp16 = 64B + 16B pad (conflict-free) */
#define MAT_BYTES (TILE * ROW_PITCH) /* 10240 */
#define A_OFF 0
#define B_OFF (MAT_BYTES)
#define STAGE_BYTES (2 * MAT_BYTES)  /* 20480 */
#define NSTAGE 3
#define SMEM_TOTAL (TILES_OFF + NSTAGE * STAGE_BYTES) /* 62720 */

__device__ float  g_sq[NROW];
__device__ float  g_colsum[DDIM];    /* zeroed by prep finisher after use */
__device__ float  g_totsq;
__device__ double g_acc[3];          /* reset by the finishing k_gemm block */
__device__ float  g_negK;            /* -log2(e)/(16*bw) */
__device__ int    g_cnt;             /* gemm finisher counter */
__device__ int    g_pcnt;            /* prep finisher counter */
__device__ __half g_h[NROW * DDIM];

__device__ __forceinline__ uint32_t smem_u32(const void* p) {
    uint32_t a;
    asm("{ .reg .u64 t; cvta.to.shared.u64 t, %1; cvt.u32.u64 %0, t; }"
        : "=r"(a) : "l"(p));
    return a;
}

#define CP_ASYNC16(dst, src) \
    asm volatile("cp.async.cg.shared.global [%0], [%1], 16;" \
                 :: "r"(dst), "l"(src) : "memory")
#define CP_COMMIT() asm volatile("cp.async.commit_group;" ::: "memory")
#define CP_WAIT(n)  asm volatile("cp.async.wait_group %0;" :: "n"(n) : "memory")

#define LDSM_X4(r, a) \
    asm volatile("ldmatrix.sync.aligned.m8n8.x4.shared.b16 {%0,%1,%2,%3}, [%4];" \
                 : "=r"((r)[0]), "=r"((r)[1]), "=r"((r)[2]), "=r"((r)[3]) : "r"(a))

/* fp16-accumulator HMMA: C/D are 2 packed-b32 regs (4 halves) */
#define MMA16816H(acc, a, b0v, b1v) \
    asm volatile("mma.sync.aligned.m16n8k16.row.col.f16.f16.f16.f16 " \
                 "{%0,%1},{%2,%3,%4,%5},{%6,%7},{%0,%1};" \
                 : "+r"((acc)[0]), "+r"((acc)[1]) \
                 : "r"((a)[0]), "r"((a)[1]), "r"((a)[2]), "r"((a)[3]), \
                   "r"(b0v), "r"(b1v))

/* ---- fused split(fp16) + rownorm + totsq + colsum + bandwidth finisher ---- */
__global__ void k_prep(const float* __restrict__ src, const float* __restrict__ tgt) {
    __shared__ float colacc[8][DDIM];
    __shared__ float bs[8];
    __shared__ int isLast;
    int warp = threadIdx.x >> 5, lane = threadIdx.x & 31;
    int row = blockIdx.x * 8 + warp;
    const float* base = (row < BHALF) ? src + (size_t)row * DDIM
                                      : tgt + (size_t)(row - BHALF) * DDIM;
    size_t orow = (size_t)row * (DDIM / 4);
    float s = 0.f;
#pragma unroll
    for (int ch = 0; ch < 4; ch++) {
        float4 v = *(const float4*)(base + ch * 128 + lane * 4);
        s += v.x * v.x + v.y * v.y + v.z * v.z + v.w * v.w;
        __half2 p0 = __floats2half2_rn(v.x, v.y);
        __half2 p1 = __floats2half2_rn(v.z, v.w);
        uint2 hv;
        hv.x = *(uint32_t*)&p0; hv.y = *(uint32_t*)&p1;
        ((uint2*)g_h)[orow + ch * 32 + lane] = hv;
        *(float4*)&colacc[warp][ch * 128 + lane * 4] = v;
    }
#pragma unroll
    for (int o = 16; o > 0; o >>= 1) s += __shfl_xor_sync(0xffffffffu, s, o);
    if (lane == 0) { g_sq[row] = s; bs[warp] = s; }
    __syncthreads();

    int c0 = threadIdx.x, c1 = threadIdx.x + 256;
    float s0 = 0.f, s1 = 0.f;
#pragma unroll
    for (int w = 0; w < 8; w++) { s0 += colacc[w][c0]; s1 += colacc[w][c1]; }
    atomicAdd(&g_colsum[c0], s0);
    atomicAdd(&g_colsum[c1], s1);

    if (threadIdx.x == 0) {
        float t = 0.f;
#pragma unroll
        for (int i = 0; i < 8; i++) t += bs[i];
        atomicAdd(&g_totsq, t);
    }

    /* ---- last block computes the bandwidth constant ---- */
    __syncthreads();
    if (threadIdx.x == 0) {
        __threadfence();
        isLast = (atomicAdd(&g_pcnt, 1) == (int)gridDim.x - 1);
    }
    __syncthreads();
    if (isLast) {
        __shared__ double wred[8];
        int t = threadIdx.x;
        float v0 = g_colsum[t], v1 = g_colsum[t + 256];
        double p = (double)v0 * v0 + (double)v1 * v1;
#pragma unroll
        for (int o = 16; o > 0; o >>= 1)
            p += __shfl_xor_sync(0xffffffffu, p, o);
        if (lane == 0) wred[warp] = p;
        __syncthreads();
        if (t == 0) {
            double tot = 0.0;
#pragma unroll
            for (int i = 0; i < 8; i++) tot += wred[i];
            double n = (double)NROW;
            double S = 2.0 * n * (double)g_totsq - 2.0 * tot;
            double bw = S / (n * n - n) / 4.0;
            g_negK = (float)(-1.4426950408889634 / (16.0 * bw));
            g_totsq = 0.f;
            g_pcnt = 0;
        }
        g_colsum[t] = 0.f;
        g_colsum[t + 256] = 0.f;
    }
}

/* ---------------------------------------------------------------- chunk loader (128 thr) */
__device__ __forceinline__ void issue_chunk(uint32_t stage_base, int rowA, int rowB,
                                            int kt, int tid) {
    const char* srcA = (const char*)(g_h + (size_t)rowA * DDIM);
    const char* srcB = (const char*)(g_h + (size_t)rowB * DDIM);
    int kbyte = kt * (BKC * 2);
#pragma unroll
    for (int i = 0; i < 4; i++) {
        int u = tid + i * 128;
        int r = u >> 2, seg = u & 3;
        size_t go = (size_t)r * (DDIM * 2) + kbyte + seg * 16;
        uint32_t so = r * ROW_PITCH + seg * 16;
        CP_ASYNC16(stage_base + A_OFF + so, srcA + go);
        CP_ASYNC16(stage_base + B_OFF + so, srcB + go);
    }
    CP_COMMIT();
}

/* ---------------------------------------------------------------- main HMMA kernel */
__global__ void __launch_bounds__(128, 3) k_gemm(float* out) {
    extern __shared__ char smem[];
    int tid = threadIdx.x;
    int lane = tid & 31, wid = tid >> 5;
    int wr = wid >> 1, wc = wid & 1;     /* 2x2 grid of 64x64 warp tiles */

    int t = blockIdx.x;
    int bi = 0, rem = t;
    while (rem >= NT2 - bi) { rem -= NT2 - bi; bi++; }
    int bj = bi + rem;
    int rowA = bi * TILE, rowB = bj * TILE;

    uint32_t sbase = smem_u32(smem);
    float* sqA = (float*)(smem + SQA_OFF);
    float* sqB = (float*)(smem + SQB_OFF);
    float* red = (float*)(smem + RED_OFF);

    if (tid < TILE) {
        sqA[tid] = g_sq[rowA + tid];
        sqB[tid] = g_sq[rowB + tid];
    }

    uint32_t aRow = wr * 64 + (lane & 7) + (lane & 8);
    uint32_t aColH = (lane & 16) >> 1;
    uint32_t bN = wc * 64 + (lane & 7) + ((lane & 16) >> 1);
    uint32_t bKoff = (lane & 8);

    /* packed fp16 accumulators */
    uint32_t acc[4][8][2];
#pragma unroll
    for (int r = 0; r < 4; r++)
#pragma unroll
        for (int j = 0; j < 8; j++) { acc[r][j][0] = 0u; acc[r][j][1] = 0u; }

    uint32_t tb = sbase + TILES_OFF;
    issue_chunk(tb, rowA, rowB, 0, tid);
    issue_chunk(tb + STAGE_BYTES, rowA, rowB, 1, tid);

    uint32_t ah[2][4][4], bh[2][4][4];

    int sidx = 0;
    for (int kt = 0; kt < NCH; kt++) {
        if (kt < NCH - 1) CP_WAIT(1); else CP_WAIT(0);
        __syncthreads();
        if (kt + 2 < NCH) {
            int ns = sidx + 2; if (ns >= NSTAGE) ns -= NSTAGE;
            issue_chunk(tb + ns * STAGE_BYTES, rowA, rowB, kt + 2, tid);
        }

        uint32_t S = tb + sidx * STAGE_BYTES;

#pragma unroll
        for (int rt = 0; rt < 4; rt++)
            LDSM_X4(ah[0][rt], S + A_OFF + (aRow + rt * 16) * ROW_PITCH + aColH * 2);
#pragma unroll
        for (int jp = 0; jp < 4; jp++)
            LDSM_X4(bh[0][jp], S + B_OFF + (bN + jp * 16) * ROW_PITCH + bKoff * 2);
#pragma unroll
        for (int rt = 0; rt < 4; rt++)
            LDSM_X4(ah[1][rt], S + A_OFF + (aRow + rt * 16) * ROW_PITCH + (16 + aColH) * 2);
#pragma unroll
        for (int jp = 0; jp < 4; jp++)
            LDSM_X4(bh[1][jp], S + B_OFF + (bN + jp * 16) * ROW_PITCH + (16 + bKoff) * 2);

#pragma unroll
        for (int rt = 0; rt < 4; rt++)
#pragma unroll
            for (int jp = 0; jp < 4; jp++) {
                MMA16816H(acc[rt][jp * 2],     ah[0][rt], bh[0][jp][0], bh[0][jp][1]);
                MMA16816H(acc[rt][jp * 2 + 1], ah[0][rt], bh[0][jp][2], bh[0][jp][3]);
            }
#pragma unroll
        for (int rt = 0; rt < 4; rt++)
#pragma unroll
            for (int jp = 0; jp < 4; jp++) {
                MMA16816H(acc[rt][jp * 2],     ah[1][rt], bh[1][jp][0], bh[1][jp][1]);
                MMA16816H(acc[rt][jp * 2 + 1], ah[1][rt], bh[1][jp][2], bh[1][jp][3]);
            }

        sidx++; if (sidx >= NSTAGE) sidx = 0;
    }

    /* -------- fused epilogue (promote fp16 acc -> fp32 here) -------- */
    float negK = g_negK;
    int g = lane >> 2, tg = lane & 3;
    float rowsq[4][2], colsq[8][2];
#pragma unroll
    for (int rt = 0; rt < 4; rt++) {
        rowsq[rt][0] = sqA[wr * 64 + rt * 16 + g];
        rowsq[rt][1] = sqA[wr * 64 + rt * 16 + g + 8];
    }
#pragma unroll
    for (int j = 0; j < 8; j++) {
        colsq[j][0] = sqB[wc * 64 + j * 8 + 2 * tg];
        colsq[j][1] = sqB[wc * 64 + j * 8 + 2 * tg + 1];
    }

    float tsum = 0.f;
#pragma unroll
    for (int rt = 0; rt < 4; rt++) {
#pragma unroll
        for (int j = 0; j < 8; j++) {
            float2 d01 = __half22float2(*(__half2*)&acc[rt][j][0]);
            float2 d23 = __half22float2(*(__half2*)&acc[rt][j][1]);
            float dv[4] = { d01.x, d01.y, d23.x, d23.y };
#pragma unroll
            for (int e = 0; e < 4; e++) {
                float sq2 = rowsq[rt][e >> 1] + colsq[j][e & 1];
                float L2v = fmaf(-2.f, dv[e], sq2);
                float s;
                asm("ex2.approx.f32 %0, %1;" : "=f"(s) : "f"(L2v * negK));
                float s2 = s * s, s4 = s2 * s2, s8 = s4 * s4, s16 = s8 * s8;
                tsum += ((s + s2) + (s4 + s8)) + s16;
            }
        }
    }
#pragma unroll
    for (int o = 16; o > 0; o >>= 1) tsum += __shfl_xor_sync(0xffffffffu, tsum, o);
    if (lane == 0) red[wid] = tsum;
    __syncthreads();

    if (tid == 0) {
        float tot = red[0] + red[1] + red[2] + red[3];
        double w = (bi == bj) ? 1.0 : 2.0;
        int qidx = (bi < NT2 / 2) ? ((bj < NT2 / 2) ? 0 : 2) : 1;
        atomicAdd(&g_acc[qidx], w * (double)tot);

        __threadfence();
        int prev = atomicAdd(&g_cnt, 1);
        if (prev == NPAIR2 - 1) {
            double bb = (double)BHALF * (double)BHALF;
            out[0] = (float)((g_acc[0] + g_acc[1] - g_acc[2]) / bb);
            g_acc[0] = 0.0; g_acc[1] = 0.0; g_acc[2] = 0.0;
            g_cnt = 0;
        }
    }
}

/* ---------------------------------------------------------------- launch */
extern "C" void kernel_launch(void* const* d_in, const int* in_sizes, int n_in,
                              void* d_out, int out_size) {
    const float* src = (const float*)d_in[0];
    const float* tgt = (const float*)d_in[1];
    float* out = (float*)d_out;

    cudaFuncSetAttribute(k_gemm, cudaFuncAttributeMaxDynamicSharedMemorySize, SMEM_TOTAL);

    k_prep<<<NROW / 8, 256>>>(src, tgt);
    k_gemm<<<NPAIR2, 128, SMEM_TOTAL>>>(out);
}

// round 16
// speedup vs baseline: 2.3061x; 1.0003x over previous
#include <cuda_runtime.h>
#include <cuda_fp16.h>
#include <math.h>
#include <stdint.h>

#define NROW 8192
#define DDIM 512
#define BHALF 4096

#define TILE 128
#define NT2 (NROW / TILE)            /* 64 */
#define NPAIR2 (NT2 * (NT2 + 1) / 2) /* 2080 */
#define BKC 32                       /* fp16 per K-chunk */
#define NCH (DDIM / BKC)             /* 16 */

#define SQA_OFF 0
#define SQB_OFF 512
#define RED_OFF 1024
#define TILES_OFF 1280
#define ROW_PITCH 80                 /* 32 fp16 = 64B + 16B pad (conflict-free) */
#define MAT_BYTES (TILE * ROW_PITCH) /* 10240 */
#define A_OFF 0
#define B_OFF (MAT_BYTES)
#define STAGE_BYTES (2 * MAT_BYTES)  /* 20480 */
#define NSTAGE 3
#define SMEM_TOTAL (TILES_OFF + NSTAGE * STAGE_BYTES) /* 62720 */

__device__ float  g_sq[NROW];
__device__ float  g_colsum[DDIM];    /* zeroed by prep finisher after use */
__device__ float  g_totsq;
__device__ double g_acc[3];          /* reset by the finishing k_gemm block */
__device__ float  g_negK;            /* -log2(e)/(16*bw) */
__device__ int    g_cnt;             /* gemm finisher counter */
__device__ int    g_pcnt;            /* prep finisher counter */
__device__ __half g_h[NROW * DDIM];

__device__ __forceinline__ uint32_t smem_u32(const void* p) {
    uint32_t a;
    asm("{ .reg .u64 t; cvta.to.shared.u64 t, %1; cvt.u32.u64 %0, t; }"
        : "=r"(a) : "l"(p));
    return a;
}

#define CP_ASYNC16(dst, src) \
    asm volatile("cp.async.cg.shared.global [%0], [%1], 16;" \
                 :: "r"(dst), "l"(src) : "memory")
#define CP_COMMIT() asm volatile("cp.async.commit_group;" ::: "memory")
#define CP_WAIT(n)  asm volatile("cp.async.wait_group %0;" :: "n"(n) : "memory")

#define LDSM_X4(r, a) \
    asm volatile("ldmatrix.sync.aligned.m8n8.x4.shared.b16 {%0,%1,%2,%3}, [%4];" \
                 : "=r"((r)[0]), "=r"((r)[1]), "=r"((r)[2]), "=r"((r)[3]) : "r"(a))

/* fp16-accumulator HMMA: C/D are 2 packed-b32 regs (4 halves) */
#define MMA16816H(acc, a, b0v, b1v) \
    asm volatile("mma.sync.aligned.m16n8k16.row.col.f16.f16.f16.f16 " \
                 "{%0,%1},{%2,%3,%4,%5},{%6,%7},{%0,%1};" \
                 : "+r"((acc)[0]), "+r"((acc)[1]) \
                 : "r"((a)[0]), "r"((a)[1]), "r"((a)[2]), "r"((a)[3]), \
                   "r"(b0v), "r"(b1v))

/* ---- fused split(fp16) + rownorm + totsq + colsum + bandwidth finisher ---- */
__global__ void k_prep(const float* __restrict__ src, const float* __restrict__ tgt) {
    __shared__ float colacc[8][DDIM];
    __shared__ float bs[8];
    __shared__ int isLast;
    int warp = threadIdx.x >> 5, lane = threadIdx.x & 31;
    int row = blockIdx.x * 8 + warp;
    const float* base = (row < BHALF) ? src + (size_t)row * DDIM
                                      : tgt + (size_t)(row - BHALF) * DDIM;
    size_t orow = (size_t)row * (DDIM / 4);
    float s = 0.f;
#pragma unroll
    for (int ch = 0; ch < 4; ch++) {
        float4 v = *(const float4*)(base + ch * 128 + lane * 4);
        s += v.x * v.x + v.y * v.y + v.z * v.z + v.w * v.w;
        __half2 p0 = __floats2half2_rn(v.x, v.y);
        __half2 p1 = __floats2half2_rn(v.z, v.w);
        uint2 hv;
        hv.x = *(uint32_t*)&p0; hv.y = *(uint32_t*)&p1;
        ((uint2*)g_h)[orow + ch * 32 + lane] = hv;
        *(float4*)&colacc[warp][ch * 128 + lane * 4] = v;
    }
#pragma unroll
    for (int o = 16; o > 0; o >>= 1) s += __shfl_xor_sync(0xffffffffu, s, o);
    if (lane == 0) { g_sq[row] = s; bs[warp] = s; }
    __syncthreads();

    /* reduce 8 warp-rows -> colacc[0][*], then one bulk-reduce to g_colsum */
    int c0 = threadIdx.x, c1 = threadIdx.x + 256;
    float s0 = 0.f, s1 = 0.f;
#pragma unroll
    for (int w = 0; w < 8; w++) { s0 += colacc[w][c0]; s1 += colacc[w][c1]; }
    colacc[0][c0] = s0;
    colacc[0][c1] = s1;
    __syncthreads();

    if (threadIdx.x == 0) {
        float t = 0.f;
#pragma unroll
        for (int i = 0; i < 8; i++) t += bs[i];
        atomicAdd(&g_totsq, t);
        /* bulk L2 reduction: 512 floats (2 KB) smem -> g_colsum */
        asm volatile(
            "cp.reduce.async.bulk.global.shared::cta.bulk_group.add.f32 [%0], [%1], %2;"
            :: "l"(g_colsum), "r"(smem_u32(&colacc[0][0])), "r"(2048)
            : "memory");
        asm volatile("cp.async.bulk.commit_group;" ::: "memory");
        asm volatile("cp.async.bulk.wait_group 0;" ::: "memory");
    }

    /* ---- last block computes the bandwidth constant ---- */
    __syncthreads();
    if (threadIdx.x == 0) {
        __threadfence();
        isLast = (atomicAdd(&g_pcnt, 1) == (int)gridDim.x - 1);
    }
    __syncthreads();
    if (isLast) {
        __shared__ double wred[8];
        int t = threadIdx.x;
        float v0 = g_colsum[t], v1 = g_colsum[t + 256];
        double p = (double)v0 * v0 + (double)v1 * v1;
#pragma unroll
        for (int o = 16; o > 0; o >>= 1)
            p += __shfl_xor_sync(0xffffffffu, p, o);
        if (lane == 0) wred[warp] = p;
        __syncthreads();
        if (t == 0) {
            double tot = 0.0;
#pragma unroll
            for (int i = 0; i < 8; i++) tot += wred[i];
            double n = (double)NROW;
            double S = 2.0 * n * (double)g_totsq - 2.0 * tot;
            double bw = S / (n * n - n) / 4.0;
            g_negK = (float)(-1.4426950408889634 / (16.0 * bw));
            g_totsq = 0.f;
            g_pcnt = 0;
        }
        g_colsum[t] = 0.f;
        g_colsum[t + 256] = 0.f;
    }
}

/* ---------------------------------------------------------------- chunk loader (128 thr) */
__device__ __forceinline__ void issue_chunk(uint32_t stage_base, int rowA, int rowB,
                                            int kt, int tid) {
    const char* srcA = (const char*)(g_h + (size_t)rowA * DDIM);
    const char* srcB = (const char*)(g_h + (size_t)rowB * DDIM);
    int kbyte = kt * (BKC * 2);
#pragma unroll
    for (int i = 0; i < 4; i++) {
        int u = tid + i * 128;
        int r = u >> 2, seg = u & 3;
        size_t go = (size_t)r * (DDIM * 2) + kbyte + seg * 16;
        uint32_t so = r * ROW_PITCH + seg * 16;
        CP_ASYNC16(stage_base + A_OFF + so, srcA + go);
        CP_ASYNC16(stage_base + B_OFF + so, srcB + go);
    }
    CP_COMMIT();
}

/* ---------------------------------------------------------------- main HMMA kernel */
__global__ void __launch_bounds__(128, 3) k_gemm(float* out) {
    extern __shared__ char smem[];
    int tid = threadIdx.x;
    int lane = tid & 31, wid = tid >> 5;
    int wr = wid >> 1, wc = wid & 1;     /* 2x2 grid of 64x64 warp tiles */

    int t = blockIdx.x;
    int bi = 0, rem = t;
    while (rem >= NT2 - bi) { rem -= NT2 - bi; bi++; }
    int bj = bi + rem;
    int rowA = bi * TILE, rowB = bj * TILE;

    uint32_t sbase = smem_u32(smem);
    float* sqA = (float*)(smem + SQA_OFF);
    float* sqB = (float*)(smem + SQB_OFF);
    float* red = (float*)(smem + RED_OFF);

    if (tid < TILE) {
        sqA[tid] = g_sq[rowA + tid];
        sqB[tid] = g_sq[rowB + tid];
    }

    uint32_t aRow = wr * 64 + (lane & 7) + (lane & 8);
    uint32_t aColH = (lane & 16) >> 1;
    uint32_t bN = wc * 64 + (lane & 7) + ((lane & 16) >> 1);
    uint32_t bKoff = (lane & 8);

    /* packed fp16 accumulators */
    uint32_t acc[4][8][2];
#pragma unroll
    for (int r = 0; r < 4; r++)
#pragma unroll
        for (int j = 0; j < 8; j++) { acc[r][j][0] = 0u; acc[r][j][1] = 0u; }

    uint32_t tb = sbase + TILES_OFF;
    issue_chunk(tb, rowA, rowB, 0, tid);
    issue_chunk(tb + STAGE_BYTES, rowA, rowB, 1, tid);

    uint32_t ah[2][4][4], bh[2][4][4];

    int sidx = 0;
    for (int kt = 0; kt < NCH; kt++) {
        if (kt < NCH - 1) CP_WAIT(1); else CP_WAIT(0);
        __syncthreads();
        if (kt + 2 < NCH) {
            int ns = sidx + 2; if (ns >= NSTAGE) ns -= NSTAGE;
            issue_chunk(tb + ns * STAGE_BYTES, rowA, rowB, kt + 2, tid);
        }

        uint32_t S = tb + sidx * STAGE_BYTES;

#pragma unroll
        for (int rt = 0; rt < 4; rt++)
            LDSM_X4(ah[0][rt], S + A_OFF + (aRow + rt * 16) * ROW_PITCH + aColH * 2);
#pragma unroll
        for (int jp = 0; jp < 4; jp++)
            LDSM_X4(bh[0][jp], S + B_OFF + (bN + jp * 16) * ROW_PITCH + bKoff * 2);
#pragma unroll
        for (int rt = 0; rt < 4; rt++)
            LDSM_X4(ah[1][rt], S + A_OFF + (aRow + rt * 16) * ROW_PITCH + (16 + aColH) * 2);
#pragma unroll
        for (int jp = 0; jp < 4; jp++)
            LDSM_X4(bh[1][jp], S + B_OFF + (bN + jp * 16) * ROW_PITCH + (16 + bKoff) * 2);

#pragma unroll
        for (int rt = 0; rt < 4; rt++)
#pragma unroll
            for (int jp = 0; jp < 4; jp++) {
                MMA16816H(acc[rt][jp * 2],     ah[0][rt], bh[0][jp][0], bh[0][jp][1]);
                MMA16816H(acc[rt][jp * 2 + 1], ah[0][rt], bh[0][jp][2], bh[0][jp][3]);
            }
#pragma unroll
        for (int rt = 0; rt < 4; rt++)
#pragma unroll
            for (int jp = 0; jp < 4; jp++) {
                MMA16816H(acc[rt][jp * 2],     ah[1][rt], bh[1][jp][0], bh[1][jp][1]);
                MMA16816H(acc[rt][jp * 2 + 1], ah[1][rt], bh[1][jp][2], bh[1][jp][3]);
            }

        sidx++; if (sidx >= NSTAGE) sidx = 0;
    }

    /* -------- fused epilogue (promote fp16 acc -> fp32 here) -------- */
    float negK = g_negK;
    int g = lane >> 2, tg = lane & 3;
    float rowsq[4][2], colsq[8][2];
#pragma unroll
    for (int rt = 0; rt < 4; rt++) {
        rowsq[rt][0] = sqA[wr * 64 + rt * 16 + g];
        rowsq[rt][1] = sqA[wr * 64 + rt * 16 + g + 8];
    }
#pragma unroll
    for (int j = 0; j < 8; j++) {
        colsq[j][0] = sqB[wc * 64 + j * 8 + 2 * tg];
        colsq[j][1] = sqB[wc * 64 + j * 8 + 2 * tg + 1];
    }

    float tsum = 0.f;
#pragma unroll
    for (int rt = 0; rt < 4; rt++) {
#pragma unroll
        for (int j = 0; j < 8; j++) {
            float2 d01 = __half22float2(*(__half2*)&acc[rt][j][0]);
            float2 d23 = __half22float2(*(__half2*)&acc[rt][j][1]);
            float dv[4] = { d01.x, d01.y, d23.x, d23.y };
#pragma unroll
            for (int e = 0; e < 4; e++) {
                float sq2 = rowsq[rt][e >> 1] + colsq[j][e & 1];
                float L2v = fmaf(-2.f, dv[e], sq2);
                float s;
                asm("ex2.approx.f32 %0, %1;" : "=f"(s) : "f"(L2v * negK));
                float s2 = s * s, s4 = s2 * s2, s8 = s4 * s4, s16 = s8 * s8;
                tsum += ((s + s2) + (s4 + s8)) + s16;
            }
        }
    }
#pragma unroll
    for (int o = 16; o > 0; o >>= 1) tsum += __shfl_xor_sync(0xffffffffu, tsum, o);
    if (lane == 0) red[wid] = tsum;
    __syncthreads();

    if (tid == 0) {
        float tot = red[0] + red[1] + red[2] + red[3];
        double w = (bi == bj) ? 1.0 : 2.0;
        int qidx = (bi < NT2 / 2) ? ((bj < NT2 / 2) ? 0 : 2) : 1;
        atomicAdd(&g_acc[qidx], w * (double)tot);

        __threadfence();
        int prev = atomicAdd(&g_cnt, 1);
        if (prev == NPAIR2 - 1) {
            double bb = (double)BHALF * (double)BHALF;
            out[0] = (float)((g_acc[0] + g_acc[1] - g_acc[2]) / bb);
            g_acc[0] = 0.0; g_acc[1] = 0.0; g_acc[2] = 0.0;
            g_cnt = 0;
        }
    }
}

/* ---------------------------------------------------------------- launch */
extern "C" void kernel_launch(void* const* d_in, const int* in_sizes, int n_in,
                              void* d_out, int out_size) {
    const float* src = (const float*)d_in[0];
    const float* tgt = (const float*)d_in[1];
    float* out = (float*)d_out;

    cudaFuncSetAttribute(k_gemm, cudaFuncAttributeMaxDynamicSharedMemorySize, SMEM_TOTAL);

    k_prep<<<NROW / 8, 256>>>(src, tgt);
    k_gemm<<<NPAIR2, 128, SMEM_TOTAL>>>(out);
}